// round 1
// baseline (speedup 1.0000x reference)
#include <cuda_runtime.h>

#define P_TOT 21824
#define R_TOT 327360
#define NB_LBL 1279

// Scratch: post-ReLU 3x3-conv features, [b][256][P_TOT] (44.7 MB)
__device__ float g_t[2 * 256 * P_TOT];
// Per-block per-gt argmax partial keys: [b][NB_LBL][32]
__device__ unsigned long long g_part[2 * NB_LBL * 32];

// ---------------------------------------------------------------------------
// 3x3 conv (pad=1) + bias + ReLU, 256->256.  Tile: 64 oc x 8x8 pixels.
// Thread: 4 oc x 4 pixels.  ic chunked by 16 through smem.
// ---------------------------------------------------------------------------
__global__ __launch_bounds__(256) void conv3x3_relu(
    const float* __restrict__ feat, const float* __restrict__ W,
    const float* __restrict__ bias, int g, int lvl_off)
{
    __shared__ __align__(16) float in_s[16][100];     // [ic][10x10 patch]
    __shared__ __align__(16) float w_s[16][9][64];    // [ic][tap][oc]
    const int t   = threadIdx.x;
    const int b   = blockIdx.z >> 2;
    const int oc0 = (blockIdx.z & 3) * 64;
    const int ti  = blockIdx.x * 8, tj = blockIdx.y * 8;
    const int og  = t & 15;        // oc quad id
    const int pg  = t >> 4;        // pixel group 0..15
    const int pj  = pg & 7;
    const int pi0 = pg >> 3;       // 0 or 1; pixels rows pi0 + 2*pp

    float acc[4][4];
    #pragma unroll
    for (int a = 0; a < 4; a++)
        #pragma unroll
        for (int q = 0; q < 4; q++) acc[a][q] = 0.f;

    const int g2 = g * g;
    const float* fb = feat + (size_t)b * 256 * g2;

    for (int ic0 = 0; ic0 < 256; ic0 += 16) {
        // load input patch (10x10 per ic, zero-padded)
        for (int idx = t; idx < 1600; idx += 256) {
            int ic = idx / 100, pos = idx - ic * 100;
            int ii = ti + pos / 10 - 1;
            int jj = tj + pos % 10 - 1;
            float v = 0.f;
            if ((unsigned)ii < (unsigned)g && (unsigned)jj < (unsigned)g)
                v = fb[(ic0 + ic) * g2 + ii * g + jj];
            in_s[ic][pos] = v;
        }
        // load weights
        for (int idx = t; idx < 16 * 9 * 64; idx += 256) {
            int oc = idx & 63, rest = idx >> 6;
            int tap = rest % 9, ic = rest / 9;
            w_s[ic][tap][oc] = W[((oc0 + oc) * 256 + ic0 + ic) * 9 + tap];
        }
        __syncthreads();

        #pragma unroll
        for (int ic = 0; ic < 16; ic++) {
            #pragma unroll
            for (int kw = 0; kw < 3; kw++) {
                float x[9];
                #pragma unroll
                for (int rr = 0; rr < 9; rr++)
                    x[rr] = in_s[ic][(pi0 + rr) * 10 + pj + kw];
                #pragma unroll
                for (int kh = 0; kh < 3; kh++) {
                    float4 w = *(const float4*)&w_s[ic][kh * 3 + kw][og * 4];
                    #pragma unroll
                    for (int pp = 0; pp < 4; pp++) {
                        float xv = x[2 * pp + kh];
                        acc[pp][0] = fmaf(w.x, xv, acc[pp][0]);
                        acc[pp][1] = fmaf(w.y, xv, acc[pp][1]);
                        acc[pp][2] = fmaf(w.z, xv, acc[pp][2]);
                        acc[pp][3] = fmaf(w.w, xv, acc[pp][3]);
                    }
                }
            }
        }
        __syncthreads();
    }

    #pragma unroll
    for (int q = 0; q < 4; q++) {
        int oc = oc0 + og * 4 + q;
        float bv = bias[oc];
        #pragma unroll
        for (int pp = 0; pp < 4; pp++) {
            int gi = ti + pi0 + 2 * pp, gj = tj + pj;
            float v = fmaxf(acc[pp][q] + bv, 0.f);
            g_t[((size_t)(b * 256 + oc)) * P_TOT + lvl_off + gi * g + gj] = v;
        }
    }
}

// ---------------------------------------------------------------------------
// 1x1 heads: 75 outputs (15 cls + 60 box) per pixel from 256 channels.
// Block: 32 pixels; warp-uniform output channel per task group.
// ---------------------------------------------------------------------------
__global__ __launch_bounds__(256) void head_kernel(
    const float* __restrict__ cls_w, const float* __restrict__ cls_b,
    const float* __restrict__ box_w, const float* __restrict__ box_b,
    float* __restrict__ preds, int g, int lvl_off)
{
    __shared__ float ts[256][32];      // [channel][pixel]
    const int t = threadIdx.x;
    const int b = blockIdx.y;
    const int pix0 = blockIdx.x * 32;
    const float* tb = g_t + ((size_t)b * 256) * P_TOT + lvl_off + pix0;
    {
        int pix = t & 31, cb = t >> 5;
        for (int c0 = 0; c0 < 256; c0 += 8) {
            int c = c0 + cb;
            ts[c][pix] = tb[(size_t)c * P_TOT + pix];
        }
    }
    __syncthreads();

    const int g2 = g * g;
    const long base_r = 15L * lvl_off;
    for (int task = t; task < 75 * 32; task += 256) {
        int o = task >> 5, pix = task & 31;
        const float* wrow; float s;
        if (o < 15) { wrow = cls_w + o * 256;        s = cls_b[o]; }
        else        { wrow = box_w + (o - 15) * 256; s = box_b[o - 15]; }
        const float4* w4 = (const float4*)wrow;
        #pragma unroll 8
        for (int c4 = 0; c4 < 64; c4++) {
            float4 w = w4[c4];
            s = fmaf(w.x, ts[c4 * 4 + 0][pix],
                fmaf(w.y, ts[c4 * 4 + 1][pix],
                fmaf(w.z, ts[c4 * 4 + 2][pix],
                fmaf(w.w, ts[c4 * 4 + 3][pix], s))));
        }
        int a, slot;
        if (o < 15) { a = o; slot = 0; }
        else        { int cch = o - 15; a = cch >> 2; slot = 1 + (cch & 3); }
        size_t r = (size_t)base_r + (size_t)a * g2 + pix0 + pix;
        preds[((size_t)b * R_TOT + r) * 5 + slot] = s;
    }
}

// ---------------------------------------------------------------------------
// Anchor labeling: per-anchor IoU vs 32 gt boxes; score/argmax/matched/labels;
// per-gt best-anchor partial reduction via packed keys (iou_bits<<32 | ~r).
// ---------------------------------------------------------------------------
__global__ __launch_bounds__(256) void label_kernel(
    const float* __restrict__ gt, float* __restrict__ labels,
    float* __restrict__ matched)
{
    __shared__ float4 gq[32];
    __shared__ float  ga[32];
    __shared__ unsigned long long skey[32];
    const int t = threadIdx.x;
    const int b = blockIdx.y;
    if (t < 32) {
        const float* p = gt + ((size_t)b * 32 + t) * 4;
        float x = p[0], y = p[1], w = p[2], h = p[3];
        float4 q = make_float4(x, y, x + w, y + h);
        gq[t] = q;
        ga[t] = (q.z - q.x) * (q.w - q.y);
        skey[t] = 0ull;
    }
    __syncthreads();

    const int r = blockIdx.x * 256 + t;
    const bool active = r < R_TOT;

    float ax1 = 0.f, ay1 = 0.f, ax2 = 1.f, ay2 = 1.f;
    if (active) {
        int base, g, shift; float stride;
        if      (r < 245760) { base = 0;      g = 128; shift = 14; stride = 4.f;  }
        else if (r < 307200) { base = 245760; g = 64;  shift = 12; stride = 8.f;  }
        else if (r < 322560) { base = 307200; g = 32;  shift = 10; stride = 16.f; }
        else if (r < 326400) { base = 322560; g = 16;  shift = 8;  stride = 32.f; }
        else                 { base = 326400; g = 8;   shift = 6;  stride = 64.f; }
        int rl = r - base;
        int a   = rl >> shift;
        int pix = rl & ((1 << shift) - 1);
        int i = pix >> (shift >> 1);
        int j = pix & (g - 1);
        int rm = a % 3;
        double rs = (rm == 0) ? 0.7071067811865476
                  : (rm == 1) ? 1.0 : 1.4142135623730951;
        float sz = (float)(32 << (a / 3));
        float aw = (float)((double)sz * rs);
        float ah = (float)((double)sz / rs);
        float cx = i * stride, cy = j * stride;
        float hw = aw * 0.5f, hh = ah * 0.5f;
        ax1 = cx - hw; ay1 = cy - hh; ax2 = cx + hw; ay2 = cy + hh;
    }
    float areaA = (ax2 - ax1) * (ay2 - ay1);
    float best = -1.f; int barg = 0;
    const unsigned rkey = active ? (unsigned)(~(unsigned)r) : 0u;

    #pragma unroll 4
    for (int n = 0; n < 32; n++) {
        float4 q = gq[n];
        float lx = fmaxf(ax1, q.x), ly = fmaxf(ay1, q.y);
        float rx = fminf(ax2, q.z), ry = fminf(ay2, q.w);
        float w  = fmaxf(rx - lx, 0.f), h = fmaxf(ry - ly, 0.f);
        float inter = w * h;
        float iou = inter / (areaA + ga[n] - inter);
        if (iou > best) { best = iou; barg = n; }    // first-index tiebreak
        unsigned long long key = active
            ? ((((unsigned long long)__float_as_uint(iou)) << 32) | rkey)
            : 0ull;
        #pragma unroll
        for (int off = 16; off; off >>= 1) {
            unsigned long long o = __shfl_down_sync(0xffffffffu, key, off);
            if (o > key) key = o;
        }
        if ((t & 31) == 0) atomicMax(&skey[n], key);
    }

    if (active) {
        float lab = (best < 0.3f) ? 0.f : ((best > 0.7f) ? 1.f : -1.f);
        labels[(size_t)b * R_TOT + r] = lab;
        float4 m = gq[barg];
        float* mp = matched + ((size_t)b * R_TOT + r) * 4;
        mp[0] = m.x; mp[1] = m.y; mp[2] = m.z; mp[3] = m.w;
    }
    __syncthreads();
    if (t < 32)
        g_part[((size_t)b * NB_LBL + blockIdx.x) * 32 + t] = skey[t];
}

// ---------------------------------------------------------------------------
// Reduce per-gt partials; promote best anchor's label to 1 unless it's a
// forced negative (label==0 means score<0.3 — torch order: neg wins).
// ---------------------------------------------------------------------------
__global__ __launch_bounds__(256) void fixup_kernel(float* __restrict__ labels)
{
    const int b = blockIdx.x >> 5;
    const int n = blockIdx.x & 31;
    unsigned long long best = 0ull;
    for (int i = threadIdx.x; i < NB_LBL; i += 256) {
        unsigned long long v = g_part[((size_t)b * NB_LBL + i) * 32 + n];
        if (v > best) best = v;
    }
    __shared__ unsigned long long sred[256];
    sred[threadIdx.x] = best;
    __syncthreads();
    for (int s = 128; s; s >>= 1) {
        if (threadIdx.x < s) {
            if (sred[threadIdx.x + s] > sred[threadIdx.x])
                sred[threadIdx.x] = sred[threadIdx.x + s];
        }
        __syncthreads();
    }
    if (threadIdx.x == 0) {
        unsigned rr = ~((unsigned)(sred[0] & 0xffffffffull));
        float* L = labels + (size_t)b * R_TOT + rr;
        if (*L != 0.f) *L = 1.f;
    }
}

// ---------------------------------------------------------------------------
extern "C" void kernel_launch(void* const* d_in, const int* in_sizes, int n_in,
                              void* d_out, int out_size)
{
    (void)in_sizes; (void)n_in; (void)out_size;
    const float* feats[5] = {(const float*)d_in[1], (const float*)d_in[2],
                             (const float*)d_in[3], (const float*)d_in[4],
                             (const float*)d_in[5]};
    const float* gt     = (const float*)d_in[6];
    const float* conv_w = (const float*)d_in[7];
    const float* conv_b = (const float*)d_in[8];
    const float* cls_w  = (const float*)d_in[9];
    const float* cls_b  = (const float*)d_in[10];
    const float* box_w  = (const float*)d_in[11];
    const float* box_b  = (const float*)d_in[12];

    float* preds   = (float*)d_out;                       // [2,R,5]
    float* labels  = preds + (size_t)2 * R_TOT * 5;       // [2,R]
    float* matched = labels + (size_t)2 * R_TOT;          // [2,R,4]

    static const int GS[5]   = {128, 64, 32, 16, 8};
    static const int POFF[5] = {0, 16384, 20480, 21504, 21760};

    for (int l = 0; l < 5; l++)
        conv3x3_relu<<<dim3(GS[l] / 8, GS[l] / 8, 8), 256>>>(
            feats[l], conv_w, conv_b, GS[l], POFF[l]);
    for (int l = 0; l < 5; l++)
        head_kernel<<<dim3(GS[l] * GS[l] / 32, 2), 256>>>(
            cls_w, cls_b, box_w, box_b, preds, GS[l], POFF[l]);
    label_kernel<<<dim3(NB_LBL, 2), 256>>>(gt, labels, matched);
    fixup_kernel<<<64, 256>>>(labels);
}

// round 3
// speedup vs baseline: 3.6075x; 3.6075x over previous
#include <cuda_runtime.h>
#include <cstdint>

#define P_TOT 21824
#define R_TOT 327360
#define NB_LBL 1279
#define NSTAGE 72

// Scratch: post-ReLU 3x3-conv features, [b][256][P_TOT] (44.7 MB)
__device__ float g_t[2 * 256 * P_TOT];
// Per-block per-gt argmax partial keys: [b][NB_LBL][32]
__device__ unsigned long long g_part[2 * NB_LBL * 32];

__device__ __forceinline__ uint32_t smem_u32(const void* p) {
    uint32_t a;
    asm("{ .reg .u64 t; cvta.to.shared.u64 t, %1; cvt.u32.u64 %0, t; }"
        : "=r"(a) : "l"(p));
    return a;
}
__device__ __forceinline__ uint32_t tf32r(float v) {
    uint32_t u;
    asm("cvt.rna.tf32.f32 %0, %1;" : "=r"(u) : "f"(v));
    return u;
}
__device__ __forceinline__ void cp_async16(uint32_t dst, const void* src) {
    asm volatile("cp.async.ca.shared.global [%0], [%1], 16;"
                 :: "r"(dst), "l"(__cvta_generic_to_global(src)) : "memory");
}
#define CP_COMMIT() asm volatile("cp.async.commit_group;" ::: "memory")
#define CP_WAIT0()  asm volatile("cp.async.wait_group 0;" ::: "memory")

__device__ __forceinline__ void mma_tf32(float* c, const uint32_t* a,
                                         uint32_t b0, uint32_t b1) {
    asm volatile(
        "mma.sync.aligned.m16n8k8.row.col.f32.tf32.tf32.f32 "
        "{%0,%1,%2,%3}, {%4,%5,%6,%7}, {%8,%9}, {%0,%1,%2,%3};"
        : "+f"(c[0]), "+f"(c[1]), "+f"(c[2]), "+f"(c[3])
        : "r"(a[0]), "r"(a[1]), "r"(a[2]), "r"(a[3]), "r"(b0), "r"(b1));
}

__device__ __forceinline__ int swz(int row, int col) {
    return row * 32 + (col ^ ((row & 7) << 2));
}

// ===================== mma tf32 implicit-GEMM conv =====================
// D[128 px, 128 oc] += A[px, k] * W[og*128+oc, k], k = ic*9 + kh*3 + kw
__global__ __launch_bounds__(256, 2) void conv_mma(
    const float* __restrict__ f0, const float* __restrict__ f1,
    const float* __restrict__ f2, const float* __restrict__ f3,
    const float* __restrict__ f4, const float* __restrict__ W,
    const float* __restrict__ bias)
{
    extern __shared__ __align__(16) uint32_t smem[];  // 2 x (A 4096 + B 4096) words
    const uint32_t smem_b = smem_u32(smem);
    const int t = threadIdx.x, lane = t & 31, warp = t >> 5;
    const int og = blockIdx.y;

    // ---- tile decode ----
    int tp = blockIdx.x;
    int b = 0;
    if (tp >= 171) { b = 1; tp -= 171; }
    int g, lg, gpix0, lvl_off, nvalid = 128;
    const float* feat;
    if      (tp < 128) { g = 128; lg = 7; lvl_off = 0;     gpix0 = tp * 128;                 feat = f0; }
    else if (tp < 160) { g = 64;  lg = 6; lvl_off = 16384; gpix0 = 16384 + (tp - 128) * 128; feat = f1; }
    else if (tp < 168) { g = 32;  lg = 5; lvl_off = 20480; gpix0 = 20480 + (tp - 160) * 128; feat = f2; }
    else if (tp < 170) { g = 16;  lg = 4; lvl_off = 21504; gpix0 = 21504 + (tp - 168) * 128; feat = f3; }
    else               { g = 8;   lg = 3; lvl_off = 21760; gpix0 = 21760;                    feat = f4; nvalid = 64; }
    const int g2 = g << lg;
    const char* fbB = (const char*)(feat + (size_t)b * 256 * g2);
    const int g2B = g2 * 4, g4 = g * 4;

    // ---- A-gather setup: thread handles row=t>>1, k-half kh=t&1 ----
    const int grow = t >> 1, kh = t & 1;
    const bool vm = grow < nvalid;
    const int pl = gpix0 - lvl_off + grow;
    const int pi = pl >> lg, pj = pl & (g - 1);
    unsigned tmask = 0;
    int base0 = ((pi - 1) * g + pj - 1) * 4;
    #pragma unroll
    for (int dr = 0; dr < 3; dr++)
        #pragma unroll
        for (int dc = 0; dc < 3; dc++) {
            int ii = pi + dr - 1, jj = pj + dc - 1;
            if (vm && (unsigned)ii < (unsigned)g && (unsigned)jj < (unsigned)g)
                tmask |= 1u << (dr * 3 + dc);
        }

    // ---- B cp.async setup: thread covers row=t>>1, cols (t&1)*16..+16 ----
    const int brow = t >> 1, bcol0 = (t & 1) * 16;
    const float* wsrc0 = W + (size_t)(og * 128 + brow) * 2304 + bcol0;

    // ---- warp tiling: 4(M) x 2(N); warp tile 32x64 ----
    const int m0 = (warp & 3) * 32, n0 = (warp >> 2) * 64;
    float acc[2][8][4];
    #pragma unroll
    for (int i = 0; i < 2; i++)
        #pragma unroll
        for (int j = 0; j < 8; j++)
            #pragma unroll
            for (int q = 0; q < 4; q++) acc[i][j][q] = 0.f;

    // gather of one chunk into registers
    auto gather = [&](int s, float* va) {
        int k0 = s * 32 + kh * 16;
        int ic = k0 / 9;
        int tap = k0 - ic * 9;
        int dr = tap / 3, dc = tap - dr * 3;
        const char* base = fbB + (size_t)ic * g2B + base0;
        #pragma unroll
        for (int kk = 0; kk < 16; kk++) {
            float x = 0.f;
            if ((tmask >> tap) & 1)
                x = __ldg((const float*)(base + dr * g4 + dc * 4));
            va[kk] = x;
            tap++; dc++;
            if (dc == 3) { dc = 0; dr++; }
            if (tap == 9) { tap = 0; dr = 0; base += g2B; }
        }
    };
    auto stsA = [&](int buf, float* va) {
        #pragma unroll
        for (int q = 0; q < 4; q++) {
            uint32_t p0 = tf32r(va[q * 4 + 0]), p1 = tf32r(va[q * 4 + 1]);
            uint32_t p2 = tf32r(va[q * 4 + 2]), p3 = tf32r(va[q * 4 + 3]);
            uint32_t addr = smem_b + (buf * 8192 + swz(grow, kh * 16 + q * 4)) * 4;
            asm volatile("st.shared.v4.b32 [%0], {%1,%2,%3,%4};"
                         :: "r"(addr), "r"(p0), "r"(p1), "r"(p2), "r"(p3) : "memory");
        }
    };
    auto ldB = [&](int s, int buf) {
        const float* src = wsrc0 + s * 32;
        #pragma unroll
        for (int j = 0; j < 4; j++) {
            uint32_t dst = smem_b + (buf * 8192 + 4096 + swz(brow, bcol0 + j * 4)) * 4;
            cp_async16(dst, src + j * 4);
        }
    };

    // ---- prologue ----
    {
        float va[16];
        gather(0, va);
        ldB(0, 0);
        CP_COMMIT();
        stsA(0, va);
        CP_WAIT0();
    }
    __syncthreads();

    // ---- mainloop ----
    for (int s = 0; s < NSTAGE; s++) {
        const int buf = s & 1, nbuf = buf ^ 1;
        float va[16];
        if (s + 1 < NSTAGE) {
            gather(s + 1, va);     // ldg latency overlaps the mma block below
            ldB(s + 1, nbuf);
            CP_COMMIT();
        }

        const uint32_t* As = smem + buf * 8192;
        const uint32_t* Bs = As + 4096;
        #pragma unroll
        for (int k8 = 0; k8 < 4; k8++) {
            uint32_t a[2][4];
            #pragma unroll
            for (int mt = 0; mt < 2; mt++) {
                int r = m0 + mt * 16 + (lane >> 2);
                int c = k8 * 8 + (lane & 3);
                a[mt][0] = As[swz(r, c)];
                a[mt][1] = As[swz(r + 8, c)];
                a[mt][2] = As[swz(r, c + 4)];
                a[mt][3] = As[swz(r + 8, c + 4)];
            }
            #pragma unroll
            for (int nt = 0; nt < 8; nt++) {
                int br = n0 + nt * 8 + (lane >> 2);
                int c = k8 * 8 + (lane & 3);
                uint32_t b0 = Bs[swz(br, c)];
                uint32_t b1 = Bs[swz(br, c + 4)];
                mma_tf32(acc[0][nt], a[0], b0, b1);
                mma_tf32(acc[1][nt], a[1], b0, b1);
            }
        }

        if (s + 1 < NSTAGE) {
            stsA(nbuf, va);
            CP_WAIT0();
        }
        __syncthreads();
    }

    // ---- epilogue: bias + ReLU -> g_t[b][oc][pix] ----
    #pragma unroll
    for (int mt = 0; mt < 2; mt++) {
        int r0 = m0 + mt * 16 + (lane >> 2);
        #pragma unroll
        for (int half = 0; half < 2; half++) {
            int r = r0 + half * 8;
            if (r < nvalid) {
                int pix = gpix0 + r;
                #pragma unroll
                for (int nt = 0; nt < 8; nt++) {
                    int c = n0 + nt * 8 + 2 * (lane & 3);
                    int oc = og * 128 + c;
                    float v0 = acc[mt][nt][half * 2 + 0] + __ldg(&bias[oc]);
                    float v1 = acc[mt][nt][half * 2 + 1] + __ldg(&bias[oc + 1]);
                    g_t[(size_t)(b * 256 + oc) * P_TOT + pix] = fmaxf(v0, 0.f);
                    g_t[(size_t)(b * 256 + oc + 1) * P_TOT + pix] = fmaxf(v1, 0.f);
                }
            }
        }
    }
}

// ---------------------------------------------------------------------------
// 1x1 heads: 75 outputs (15 cls + 60 box) per pixel from 256 channels.
// ---------------------------------------------------------------------------
__global__ __launch_bounds__(256) void head_kernel(
    const float* __restrict__ cls_w, const float* __restrict__ cls_b,
    const float* __restrict__ box_w, const float* __restrict__ box_b,
    float* __restrict__ preds, int g, int lvl_off)
{
    __shared__ float ts[256][32];
    const int t = threadIdx.x;
    const int b = blockIdx.y;
    const int pix0 = blockIdx.x * 32;
    const float* tb = g_t + ((size_t)b * 256) * P_TOT + lvl_off + pix0;
    {
        int pix = t & 31, cb = t >> 5;
        for (int c0 = 0; c0 < 256; c0 += 8) {
            int c = c0 + cb;
            ts[c][pix] = tb[(size_t)c * P_TOT + pix];
        }
    }
    __syncthreads();

    const int g2 = g * g;
    const long base_r = 15L * lvl_off;
    for (int task = t; task < 75 * 32; task += 256) {
        int o = task >> 5, pix = task & 31;
        const float* wrow; float s;
        if (o < 15) { wrow = cls_w + o * 256;        s = cls_b[o]; }
        else        { wrow = box_w + (o - 15) * 256; s = box_b[o - 15]; }
        const float4* w4 = (const float4*)wrow;
        #pragma unroll 8
        for (int c4 = 0; c4 < 64; c4++) {
            float4 w = w4[c4];
            s = fmaf(w.x, ts[c4 * 4 + 0][pix],
                fmaf(w.y, ts[c4 * 4 + 1][pix],
                fmaf(w.z, ts[c4 * 4 + 2][pix],
                fmaf(w.w, ts[c4 * 4 + 3][pix], s))));
        }
        int a, slot;
        if (o < 15) { a = o; slot = 0; }
        else        { int cch = o - 15; a = cch >> 2; slot = 1 + (cch & 3); }
        size_t r = (size_t)base_r + (size_t)a * g2 + pix0 + pix;
        preds[((size_t)b * R_TOT + r) * 5 + slot] = s;
    }
}

// ---------------------------------------------------------------------------
// Anchor labeling (unchanged, verified R1)
// ---------------------------------------------------------------------------
__global__ __launch_bounds__(256) void label_kernel(
    const float* __restrict__ gt, float* __restrict__ labels,
    float* __restrict__ matched)
{
    __shared__ float4 gq[32];
    __shared__ float  ga[32];
    __shared__ unsigned long long skey[32];
    const int t = threadIdx.x;
    const int b = blockIdx.y;
    if (t < 32) {
        const float* p = gt + ((size_t)b * 32 + t) * 4;
        float x = p[0], y = p[1], w = p[2], h = p[3];
        float4 q = make_float4(x, y, x + w, y + h);
        gq[t] = q;
        ga[t] = (q.z - q.x) * (q.w - q.y);
        skey[t] = 0ull;
    }
    __syncthreads();

    const int r = blockIdx.x * 256 + t;
    const bool active = r < R_TOT;

    float ax1 = 0.f, ay1 = 0.f, ax2 = 1.f, ay2 = 1.f;
    if (active) {
        int base, g, shift; float stride;
        if      (r < 245760) { base = 0;      g = 128; shift = 14; stride = 4.f;  }
        else if (r < 307200) { base = 245760; g = 64;  shift = 12; stride = 8.f;  }
        else if (r < 322560) { base = 307200; g = 32;  shift = 10; stride = 16.f; }
        else if (r < 326400) { base = 322560; g = 16;  shift = 8;  stride = 32.f; }
        else                 { base = 326400; g = 8;   shift = 6;  stride = 64.f; }
        int rl = r - base;
        int a   = rl >> shift;
        int pix = rl & ((1 << shift) - 1);
        int i = pix >> (shift >> 1);
        int j = pix & (g - 1);
        int rm = a % 3;
        double rs = (rm == 0) ? 0.7071067811865476
                  : (rm == 1) ? 1.0 : 1.4142135623730951;
        float sz = (float)(32 << (a / 3));
        float aw = (float)((double)sz * rs);
        float ah = (float)((double)sz / rs);
        float cx = i * stride, cy = j * stride;
        float hw = aw * 0.5f, hh = ah * 0.5f;
        ax1 = cx - hw; ay1 = cy - hh; ax2 = cx + hw; ay2 = cy + hh;
    }
    float areaA = (ax2 - ax1) * (ay2 - ay1);
    float best = -1.f; int barg = 0;
    const unsigned rkey = active ? (unsigned)(~(unsigned)r) : 0u;

    #pragma unroll 4
    for (int n = 0; n < 32; n++) {
        float4 q = gq[n];
        float lx = fmaxf(ax1, q.x), ly = fmaxf(ay1, q.y);
        float rx = fminf(ax2, q.z), ry = fminf(ay2, q.w);
        float w  = fmaxf(rx - lx, 0.f), h = fmaxf(ry - ly, 0.f);
        float inter = w * h;
        float iou = inter / (areaA + ga[n] - inter);
        if (iou > best) { best = iou; barg = n; }
        unsigned long long key = active
            ? ((((unsigned long long)__float_as_uint(iou)) << 32) | rkey)
            : 0ull;
        #pragma unroll
        for (int off = 16; off; off >>= 1) {
            unsigned long long o = __shfl_down_sync(0xffffffffu, key, off);
            if (o > key) key = o;
        }
        if ((t & 31) == 0) atomicMax(&skey[n], key);
    }

    if (active) {
        float lab = (best < 0.3f) ? 0.f : ((best > 0.7f) ? 1.f : -1.f);
        labels[(size_t)b * R_TOT + r] = lab;
        float4 mm = gq[barg];
        float* mp = matched + ((size_t)b * R_TOT + r) * 4;
        mp[0] = mm.x; mp[1] = mm.y; mp[2] = mm.z; mp[3] = mm.w;
    }
    __syncthreads();
    if (t < 32)
        g_part[((size_t)b * NB_LBL + blockIdx.x) * 32 + t] = skey[t];
}

__global__ __launch_bounds__(256) void fixup_kernel(float* __restrict__ labels)
{
    const int b = blockIdx.x >> 5;
    const int n = blockIdx.x & 31;
    unsigned long long best = 0ull;
    for (int i = threadIdx.x; i < NB_LBL; i += 256) {
        unsigned long long v = g_part[((size_t)b * NB_LBL + i) * 32 + n];
        if (v > best) best = v;
    }
    __shared__ unsigned long long sred[256];
    sred[threadIdx.x] = best;
    __syncthreads();
    for (int s = 128; s; s >>= 1) {
        if (threadIdx.x < s) {
            if (sred[threadIdx.x + s] > sred[threadIdx.x])
                sred[threadIdx.x] = sred[threadIdx.x + s];
        }
        __syncthreads();
    }
    if (threadIdx.x == 0) {
        unsigned rr = ~((unsigned)(sred[0] & 0xffffffffull));
        float* L = labels + (size_t)b * R_TOT + rr;
        if (*L != 0.f) *L = 1.f;
    }
}

// ---------------------------------------------------------------------------
extern "C" void kernel_launch(void* const* d_in, const int* in_sizes, int n_in,
                              void* d_out, int out_size)
{
    (void)in_sizes; (void)n_in; (void)out_size;
    const float* f0     = (const float*)d_in[1];
    const float* f1     = (const float*)d_in[2];
    const float* f2     = (const float*)d_in[3];
    const float* f3     = (const float*)d_in[4];
    const float* f4     = (const float*)d_in[5];
    const float* gt     = (const float*)d_in[6];
    const float* conv_w = (const float*)d_in[7];
    const float* conv_b = (const float*)d_in[8];
    const float* cls_w  = (const float*)d_in[9];
    const float* cls_b  = (const float*)d_in[10];
    const float* box_w  = (const float*)d_in[11];
    const float* box_b  = (const float*)d_in[12];

    float* preds   = (float*)d_out;                       // [2,R,5]
    float* labels  = preds + (size_t)2 * R_TOT * 5;       // [2,R]
    float* matched = labels + (size_t)2 * R_TOT;          // [2,R,4]

    static const int GS[5]   = {128, 64, 32, 16, 8};
    static const int POFF[5] = {0, 16384, 20480, 21504, 21760};

    cudaFuncSetAttribute(conv_mma, cudaFuncAttributeMaxDynamicSharedMemorySize,
                         65536);
    conv_mma<<<dim3(342, 2), 256, 65536>>>(f0, f1, f2, f3, f4, conv_w, conv_b);

    for (int l = 0; l < 5; l++)
        head_kernel<<<dim3(GS[l] * GS[l] / 32, 2), 256>>>(
            cls_w, cls_b, box_w, box_b, preds, GS[l], POFF[l]);
    label_kernel<<<dim3(NB_LBL, 2), 256>>>(gt, labels, matched);
    fixup_kernel<<<64, 256>>>(labels);
}

// round 4
// speedup vs baseline: 6.1722x; 1.7109x over previous
#include <cuda_runtime.h>
#include <cuda_fp16.h>
#include <cstdint>

#define P_TOT 21824
#define R_TOT 327360
#define NB_LBL 1279
#define NSTAGE 72

// Scratch
__device__ float g_t[2 * 256 * P_TOT];                 // post-ReLU conv out, f32
__device__ __half g_fh[2 * 256 * P_TOT];               // feats as half
__device__ __half g_wh[256 * 2304];                    // conv_w as half
__device__ unsigned long long g_part[2 * NB_LBL * 32];

__device__ __forceinline__ uint32_t smem_u32(const void* p) {
    uint32_t a;
    asm("{ .reg .u64 t; cvta.to.shared.u64 t, %1; cvt.u32.u64 %0, t; }"
        : "=r"(a) : "l"(p));
    return a;
}
__device__ __forceinline__ void cp_async16(uint32_t dst, const void* src) {
    asm volatile("cp.async.ca.shared.global [%0], [%1], 16;"
                 :: "r"(dst), "l"(__cvta_generic_to_global(src)) : "memory");
}
#define CP_COMMIT() asm volatile("cp.async.commit_group;" ::: "memory")
#define CP_WAIT0()  asm volatile("cp.async.wait_group 0;" ::: "memory")

__device__ __forceinline__ void ldm4(uint32_t* r, uint32_t addr) {
    asm volatile("ldmatrix.sync.aligned.m8n8.x4.shared.b16 {%0,%1,%2,%3}, [%4];"
                 : "=r"(r[0]), "=r"(r[1]), "=r"(r[2]), "=r"(r[3]) : "r"(addr));
}
__device__ __forceinline__ void mma_f16(float* c, const uint32_t* a,
                                        uint32_t b0, uint32_t b1) {
    asm volatile(
        "mma.sync.aligned.m16n8k16.row.col.f32.f16.f16.f32 "
        "{%0,%1,%2,%3}, {%4,%5,%6,%7}, {%8,%9}, {%0,%1,%2,%3};"
        : "+f"(c[0]), "+f"(c[1]), "+f"(c[2]), "+f"(c[3])
        : "r"(a[0]), "r"(a[1]), "r"(a[2]), "r"(a[3]), "r"(b0), "r"(b1));
}
// tile rows = 32 halfs = 64B = 4 chunks of 16B; conflict-free swizzle
__device__ __forceinline__ uint32_t swzH(int row, int chunk) {
    return (uint32_t)((row << 6) + (((chunk ^ ((row >> 1) & 3)) & 3) << 4));
}

// ===================== pre-conversion kernels =====================
__global__ __launch_bounds__(1024) void convW_kernel(const float* __restrict__ W) {
    int i = blockIdx.x * 1024 + threadIdx.x;
    if (i < 256 * 2304) g_wh[i] = __float2half(W[i]);
}

__global__ __launch_bounds__(256) void convF_kernel(
    const float* __restrict__ f0, const float* __restrict__ f1,
    const float* __restrict__ f2, const float* __restrict__ f3,
    const float* __restrict__ f4)
{
    const int b = blockIdx.y;
    const int px0 = blockIdx.x * 64;
    int g2, lvl_off; const float* feat;
    if      (px0 < 16384) { g2 = 16384; lvl_off = 0;     feat = f0; }
    else if (px0 < 20480) { g2 = 4096;  lvl_off = 16384; feat = f1; }
    else if (px0 < 21504) { g2 = 1024;  lvl_off = 20480; feat = f2; }
    else if (px0 < 21760) { g2 = 256;   lvl_off = 21504; feat = f3; }
    else                  { g2 = 64;    lvl_off = 21760; feat = f4; }
    const int t = threadIdx.x;
    const int px = px0 + (t & 63), c0 = t >> 6;
    const int lp = px - lvl_off;
    for (int c = c0; c < 256; c += 4) {
        float v = feat[(size_t)(b * 256 + c) * g2 + lp];
        g_fh[(size_t)(b * 256 + c) * P_TOT + px] = __float2half(v);
    }
}

// ===================== fp16 mma implicit-GEMM conv =====================
// D[128 px, 128 oc] += A[px,k] * W[og*128+oc,k], k = ic*9 + kh*3 + kw (2304)
__global__ __launch_bounds__(256, 2) void conv_mma(const float* __restrict__ bias)
{
    extern __shared__ __align__(16) char smem[];
    const uint32_t smem_b = smem_u32(smem);
    const int t = threadIdx.x, lane = t & 31, warp = t >> 5;
    const int og = blockIdx.y;

    // ---- tile decode ----
    int tp = blockIdx.x;
    int b = 0;
    if (tp >= 171) { b = 1; tp -= 171; }
    int g, lg, gpix0, lvl_off, nvalid = 128;
    if      (tp < 128) { g = 128; lg = 7; lvl_off = 0;     gpix0 = tp * 128; }
    else if (tp < 160) { g = 64;  lg = 6; lvl_off = 16384; gpix0 = 16384 + (tp - 128) * 128; }
    else if (tp < 168) { g = 32;  lg = 5; lvl_off = 20480; gpix0 = 20480 + (tp - 160) * 128; }
    else if (tp < 170) { g = 16;  lg = 4; lvl_off = 21504; gpix0 = 21504 + (tp - 168) * 128; }
    else               { g = 8;   lg = 3; lvl_off = 21760; gpix0 = 21760; nvalid = 64; }
    const char* fbB = (const char*)(g_fh + (size_t)(b * 256) * P_TOT + lvl_off);
    const int icB = P_TOT * 2, gB = g * 2;

    // ---- A-gather setup: thread = (row grow, k-half kh) ----
    const int grow = t >> 1, kh = t & 1;
    const bool vm = grow < nvalid;
    const int pl = gpix0 - lvl_off + grow;
    const int pi = pl >> lg, pj = pl & (g - 1);
    unsigned tmask = 0;
    const int base0 = ((pi - 1) * g + pj - 1) * 2;
    #pragma unroll
    for (int dr = 0; dr < 3; dr++)
        #pragma unroll
        for (int dc = 0; dc < 3; dc++) {
            int ii = pi + dr - 1, jj = pj + dc - 1;
            if (vm && (unsigned)ii < (unsigned)g && (unsigned)jj < (unsigned)g)
                tmask |= 1u << (dr * 3 + dc);
        }

    // ---- B cp.async setup ----
    const int brow = t >> 1;
    const __half* wsrc = g_wh + (size_t)(og * 128 + brow) * 2304 + kh * 16;

    // ---- warp tiling: 4(M) x 2(N), warp tile 32x64 ----
    const int m0 = (warp & 3) * 32, n0 = (warp >> 2) * 64;
    float acc[2][8][4];
    #pragma unroll
    for (int i = 0; i < 2; i++)
        #pragma unroll
        for (int j = 0; j < 8; j++)
            #pragma unroll
            for (int q = 0; q < 4; q++) acc[i][j][q] = 0.f;

    auto gather = [&](int s, uint32_t* va) {
        int k0 = s * 32 + kh * 16;
        int ic = k0 / 9;
        int tap = k0 - ic * 9;
        int dr = tap / 3, dc = tap - dr * 3;
        const char* base = fbB + (size_t)ic * icB + base0;
        unsigned short v[16];
        #pragma unroll
        for (int kk = 0; kk < 16; kk++) {
            unsigned short x = 0;
            if ((tmask >> tap) & 1)
                x = __ldg((const unsigned short*)(base + dr * gB + dc * 2));
            v[kk] = x;
            tap++; dc++;
            if (dc == 3) { dc = 0; dr++; }
            if (tap == 9) { tap = 0; dr = 0; base += icB; }
        }
        #pragma unroll
        for (int q = 0; q < 8; q++)
            va[q] = (uint32_t)v[2 * q] | ((uint32_t)v[2 * q + 1] << 16);
    };
    auto stsA = [&](int buf, uint32_t* va) {
        uint32_t Ab = smem_b + buf * 16384;
        #pragma unroll
        for (int j = 0; j < 2; j++) {
            uint32_t addr = Ab + swzH(grow, 2 * kh + j);
            asm volatile("st.shared.v4.b32 [%0], {%1,%2,%3,%4};"
                         :: "r"(addr), "r"(va[4 * j]), "r"(va[4 * j + 1]),
                            "r"(va[4 * j + 2]), "r"(va[4 * j + 3]) : "memory");
        }
    };
    auto ldB = [&](int s, int buf) {
        uint32_t Bb = smem_b + buf * 16384 + 8192;
        const __half* src = wsrc + s * 32;
        #pragma unroll
        for (int j = 0; j < 2; j++)
            cp_async16(Bb + swzH(brow, 2 * kh + j), src + j * 8);
    };

    // ---- prologue ----
    {
        uint32_t va[8];
        gather(0, va);
        ldB(0, 0);
        CP_COMMIT();
        stsA(0, va);
        CP_WAIT0();
    }
    __syncthreads();

    // ---- mainloop ----
    for (int s = 0; s < NSTAGE; s++) {
        const int buf = s & 1, nbuf = buf ^ 1;
        uint32_t va[8];
        if (s + 1 < NSTAGE) {
            gather(s + 1, va);
            ldB(s + 1, nbuf);
            CP_COMMIT();
        }

        const uint32_t As = smem_b + buf * 16384;
        const uint32_t Bs = As + 8192;
        #pragma unroll
        for (int k16 = 0; k16 < 2; k16++) {
            uint32_t a[2][4];
            #pragma unroll
            for (int mt = 0; mt < 2; mt++)
                ldm4(a[mt], As + swzH(m0 + mt * 16 + (lane & 15),
                                      k16 * 2 + (lane >> 4)));
            #pragma unroll
            for (int np = 0; np < 4; np++) {
                uint32_t bb[4];
                ldm4(bb, Bs + swzH(n0 + np * 16 + ((lane >> 4) & 1) * 8 + (lane & 7),
                                   k16 * 2 + ((lane >> 3) & 1)));
                mma_f16(acc[0][2 * np],     a[0], bb[0], bb[1]);
                mma_f16(acc[1][2 * np],     a[1], bb[0], bb[1]);
                mma_f16(acc[0][2 * np + 1], a[0], bb[2], bb[3]);
                mma_f16(acc[1][2 * np + 1], a[1], bb[2], bb[3]);
            }
        }

        if (s + 1 < NSTAGE) {
            stsA(nbuf, va);
            CP_WAIT0();
        }
        __syncthreads();
    }

    // ---- epilogue: bias + ReLU -> g_t[b][oc][pix] ----
    #pragma unroll
    for (int mt = 0; mt < 2; mt++) {
        int r0 = m0 + mt * 16 + (lane >> 2);
        #pragma unroll
        for (int half = 0; half < 2; half++) {
            int r = r0 + half * 8;
            if (r < nvalid) {
                int pix = gpix0 + r;
                #pragma unroll
                for (int nt = 0; nt < 8; nt++) {
                    int c = n0 + nt * 8 + 2 * (lane & 3);
                    int oc = og * 128 + c;
                    float v0 = acc[mt][nt][half * 2 + 0] + __ldg(&bias[oc]);
                    float v1 = acc[mt][nt][half * 2 + 1] + __ldg(&bias[oc + 1]);
                    g_t[(size_t)(b * 256 + oc) * P_TOT + pix] = fmaxf(v0, 0.f);
                    g_t[(size_t)(b * 256 + oc + 1) * P_TOT + pix] = fmaxf(v1, 0.f);
                }
            }
        }
    }
}

// ---------------------------------------------------------------------------
// Heads, single launch: block = 128 px x 80 outs (75 used), K=256 chunked 32.
// thread: o0 = (t&15)*5, p0 = 8*(t>>4); 40 accumulators.
// ---------------------------------------------------------------------------
__global__ __launch_bounds__(256) void head_kernel(
    const float* __restrict__ cls_w, const float* __restrict__ cls_b,
    const float* __restrict__ box_w, const float* __restrict__ box_b,
    float* __restrict__ preds)
{
    __shared__ float Xs[32][128];
    __shared__ float Ws[32][80];
    const int t = threadIdx.x;
    const int b = blockIdx.y;
    const int gpx0 = blockIdx.x * 128;

    int g2, lvl_off, nvalid = 128;
    if      (gpx0 < 16384) { g2 = 16384; lvl_off = 0; }
    else if (gpx0 < 20480) { g2 = 4096;  lvl_off = 16384; }
    else if (gpx0 < 21504) { g2 = 1024;  lvl_off = 20480; }
    else if (gpx0 < 21760) { g2 = 256;   lvl_off = 21504; }
    else                   { g2 = 64;    lvl_off = 21760; nvalid = 64; }

    const int o0 = (t & 15) * 5, p0 = 8 * (t >> 4);
    float acc[5][8];
    #pragma unroll
    for (int j = 0; j < 5; j++)
        #pragma unroll
        for (int p = 0; p < 8; p++) acc[j][p] = 0.f;

    for (int c0 = 0; c0 < 256; c0 += 32) {
        // load X tile
        #pragma unroll
        for (int i = 0; i < 16; i++) {
            int idx = t + i * 256;
            int ci = idx >> 7, px = idx & 127;
            int gp = gpx0 + px;
            Xs[ci][px] = (gp < P_TOT)
                ? g_t[(size_t)(b * 256 + c0 + ci) * P_TOT + gp] : 0.f;
        }
        // load W tile [ci][o]
        #pragma unroll
        for (int i = 0; i < 10; i++) {
            int idx = t + i * 256;
            int ci = idx / 80, o = idx - ci * 80;
            float w = 0.f;
            if (o < 15)      w = cls_w[o * 256 + c0 + ci];
            else if (o < 75) w = box_w[(o - 15) * 256 + c0 + ci];
            Ws[ci][o] = w;
        }
        __syncthreads();
        #pragma unroll 4
        for (int ci = 0; ci < 32; ci++) {
            float4 x0 = *(const float4*)&Xs[ci][p0];
            float4 x1 = *(const float4*)&Xs[ci][p0 + 4];
            float xv[8] = {x0.x, x0.y, x0.z, x0.w, x1.x, x1.y, x1.z, x1.w};
            #pragma unroll
            for (int j = 0; j < 5; j++) {
                float w = Ws[ci][o0 + j];
                #pragma unroll
                for (int p = 0; p < 8; p++)
                    acc[j][p] = fmaf(w, xv[p], acc[j][p]);
            }
        }
        __syncthreads();
    }

    const long base_r = 15L * lvl_off;
    #pragma unroll
    for (int j = 0; j < 5; j++) {
        int o = o0 + j;
        if (o < 75) {
            int a, slot; float bv;
            if (o < 15) { a = o; slot = 0; bv = cls_b[o]; }
            else { int cch = o - 15; a = cch >> 2; slot = 1 + (cch & 3); bv = box_b[cch]; }
            #pragma unroll
            for (int p = 0; p < 8; p++) {
                int pl = p0 + p;
                if (pl < nvalid) {
                    size_t r = (size_t)base_r + (size_t)a * g2 + (gpx0 + pl - lvl_off);
                    preds[((size_t)b * R_TOT + r) * 5 + slot] = acc[j][p] + bv;
                }
            }
        }
    }
}

// ---------------------------------------------------------------------------
// Anchor labeling (unchanged, verified R1/R3)
// ---------------------------------------------------------------------------
__global__ __launch_bounds__(256) void label_kernel(
    const float* __restrict__ gt, float* __restrict__ labels,
    float* __restrict__ matched)
{
    __shared__ float4 gq[32];
    __shared__ float  ga[32];
    __shared__ unsigned long long skey[32];
    const int t = threadIdx.x;
    const int b = blockIdx.y;
    if (t < 32) {
        const float* p = gt + ((size_t)b * 32 + t) * 4;
        float x = p[0], y = p[1], w = p[2], h = p[3];
        float4 q = make_float4(x, y, x + w, y + h);
        gq[t] = q;
        ga[t] = (q.z - q.x) * (q.w - q.y);
        skey[t] = 0ull;
    }
    __syncthreads();

    const int r = blockIdx.x * 256 + t;
    const bool active = r < R_TOT;

    float ax1 = 0.f, ay1 = 0.f, ax2 = 1.f, ay2 = 1.f;
    if (active) {
        int base, g, shift; float stride;
        if      (r < 245760) { base = 0;      g = 128; shift = 14; stride = 4.f;  }
        else if (r < 307200) { base = 245760; g = 64;  shift = 12; stride = 8.f;  }
        else if (r < 322560) { base = 307200; g = 32;  shift = 10; stride = 16.f; }
        else if (r < 326400) { base = 322560; g = 16;  shift = 8;  stride = 32.f; }
        else                 { base = 326400; g = 8;   shift = 6;  stride = 64.f; }
        int rl = r - base;
        int a   = rl >> shift;
        int pix = rl & ((1 << shift) - 1);
        int i = pix >> (shift >> 1);
        int j = pix & (g - 1);
        int rm = a % 3;
        double rs = (rm == 0) ? 0.7071067811865476
                  : (rm == 1) ? 1.0 : 1.4142135623730951;
        float sz = (float)(32 << (a / 3));
        float aw = (float)((double)sz * rs);
        float ah = (float)((double)sz / rs);
        float cx = i * stride, cy = j * stride;
        float hw = aw * 0.5f, hh = ah * 0.5f;
        ax1 = cx - hw; ay1 = cy - hh; ax2 = cx + hw; ay2 = cy + hh;
    }
    float areaA = (ax2 - ax1) * (ay2 - ay1);
    float best = -1.f; int barg = 0;
    const unsigned rkey = active ? (unsigned)(~(unsigned)r) : 0u;

    #pragma unroll 4
    for (int n = 0; n < 32; n++) {
        float4 q = gq[n];
        float lx = fmaxf(ax1, q.x), ly = fmaxf(ay1, q.y);
        float rx = fminf(ax2, q.z), ry = fminf(ay2, q.w);
        float w  = fmaxf(rx - lx, 0.f), h = fmaxf(ry - ly, 0.f);
        float inter = w * h;
        float iou = inter / (areaA + ga[n] - inter);
        if (iou > best) { best = iou; barg = n; }
        unsigned long long key = active
            ? ((((unsigned long long)__float_as_uint(iou)) << 32) | rkey)
            : 0ull;
        #pragma unroll
        for (int off = 16; off; off >>= 1) {
            unsigned long long o = __shfl_down_sync(0xffffffffu, key, off);
            if (o > key) key = o;
        }
        if ((t & 31) == 0) atomicMax(&skey[n], key);
    }

    if (active) {
        float lab = (best < 0.3f) ? 0.f : ((best > 0.7f) ? 1.f : -1.f);
        labels[(size_t)b * R_TOT + r] = lab;
        float4 mm = gq[barg];
        float* mp = matched + ((size_t)b * R_TOT + r) * 4;
        mp[0] = mm.x; mp[1] = mm.y; mp[2] = mm.z; mp[3] = mm.w;
    }
    __syncthreads();
    if (t < 32)
        g_part[((size_t)b * NB_LBL + blockIdx.x) * 32 + t] = skey[t];
}

__global__ __launch_bounds__(256) void fixup_kernel(float* __restrict__ labels)
{
    const int b = blockIdx.x >> 5;
    const int n = blockIdx.x & 31;
    unsigned long long best = 0ull;
    for (int i = threadIdx.x; i < NB_LBL; i += 256) {
        unsigned long long v = g_part[((size_t)b * NB_LBL + i) * 32 + n];
        if (v > best) best = v;
    }
    __shared__ unsigned long long sred[256];
    sred[threadIdx.x] = best;
    __syncthreads();
    for (int s = 128; s; s >>= 1) {
        if (threadIdx.x < s) {
            if (sred[threadIdx.x + s] > sred[threadIdx.x])
                sred[threadIdx.x] = sred[threadIdx.x + s];
        }
        __syncthreads();
    }
    if (threadIdx.x == 0) {
        unsigned rr = ~((unsigned)(sred[0] & 0xffffffffull));
        float* L = labels + (size_t)b * R_TOT + rr;
        if (*L != 0.f) *L = 1.f;
    }
}

// ---------------------------------------------------------------------------
extern "C" void kernel_launch(void* const* d_in, const int* in_sizes, int n_in,
                              void* d_out, int out_size)
{
    (void)in_sizes; (void)n_in; (void)out_size;
    const float* f0     = (const float*)d_in[1];
    const float* f1     = (const float*)d_in[2];
    const float* f2     = (const float*)d_in[3];
    const float* f3     = (const float*)d_in[4];
    const float* f4     = (const float*)d_in[5];
    const float* gt     = (const float*)d_in[6];
    const float* conv_w = (const float*)d_in[7];
    const float* conv_b = (const float*)d_in[8];
    const float* cls_w  = (const float*)d_in[9];
    const float* cls_b  = (const float*)d_in[10];
    const float* box_w  = (const float*)d_in[11];
    const float* box_b  = (const float*)d_in[12];

    float* preds   = (float*)d_out;                       // [2,R,5]
    float* labels  = preds + (size_t)2 * R_TOT * 5;       // [2,R]
    float* matched = labels + (size_t)2 * R_TOT;          // [2,R,4]

    convW_kernel<<<576, 1024>>>(conv_w);
    convF_kernel<<<dim3(341, 2), 256>>>(f0, f1, f2, f3, f4);

    cudaFuncSetAttribute(conv_mma, cudaFuncAttributeMaxDynamicSharedMemorySize,
                         32768);
    conv_mma<<<dim3(342, 2), 256, 32768>>>(conv_b);

    head_kernel<<<dim3(171, 2), 256>>>(cls_w, cls_b, box_w, box_b, preds);
    label_kernel<<<dim3(NB_LBL, 2), 256>>>(gt, labels, matched);
    fixup_kernel<<<64, 256>>>(labels);
}

// round 5
// speedup vs baseline: 10.3291x; 1.6735x over previous
#include <cuda_runtime.h>
#include <cuda_fp16.h>
#include <cstdint>

#define P_TOT 21824
#define R_TOT 327360
#define NB_LBL 1279
#define NSTAGE 72

// Scratch
__device__ __half g_fh[2 * P_TOT * 256];   // feats, NHWC half: [b][px][c]
__device__ __half g_th[2 * P_TOT * 256];   // conv out (ReLU), NHWC half
__device__ __half g_wh[256 * 2304];        // conv_w reordered: [oc][tap*256+ic]
__device__ __half g_hb[8 * 80 * 32];       // head W, pre-swizzled [ks][o][32]
__device__ unsigned long long g_part[2 * NB_LBL * 32];

__device__ __forceinline__ uint32_t smem_u32(const void* p) {
    uint32_t a;
    asm("{ .reg .u64 t; cvta.to.shared.u64 t, %1; cvt.u32.u64 %0, t; }"
        : "=r"(a) : "l"(p));
    return a;
}
__device__ __forceinline__ void cp_async16(uint32_t dst, const void* src) {
    asm volatile("cp.async.ca.shared.global [%0], [%1], 16;"
                 :: "r"(dst), "l"(__cvta_generic_to_global(src)) : "memory");
}
__device__ __forceinline__ void cp_async16z(uint32_t dst, const void* src,
                                            uint32_t sz) {
    asm volatile("cp.async.ca.shared.global [%0], [%1], 16, %2;"
                 :: "r"(dst), "l"(__cvta_generic_to_global(src)), "r"(sz)
                 : "memory");
}
#define CP_COMMIT() asm volatile("cp.async.commit_group;" ::: "memory")
#define CP_WAIT(n)  asm volatile("cp.async.wait_group %0;" :: "n"(n) : "memory")

__device__ __forceinline__ void ldm4(uint32_t* r, uint32_t addr) {
    asm volatile("ldmatrix.sync.aligned.m8n8.x4.shared.b16 {%0,%1,%2,%3}, [%4];"
                 : "=r"(r[0]), "=r"(r[1]), "=r"(r[2]), "=r"(r[3]) : "r"(addr));
}
__device__ __forceinline__ void mma_f16(float* c, const uint32_t* a,
                                        uint32_t b0, uint32_t b1) {
    asm volatile(
        "mma.sync.aligned.m16n8k16.row.col.f32.f16.f16.f32 "
        "{%0,%1,%2,%3}, {%4,%5,%6,%7}, {%8,%9}, {%0,%1,%2,%3};"
        : "+f"(c[0]), "+f"(c[1]), "+f"(c[2]), "+f"(c[3])
        : "r"(a[0]), "r"(a[1]), "r"(a[2]), "r"(a[3]), "r"(b0), "r"(b1));
}
// rows of 32 halfs (64B = 4 chunks of 16B); conflict-free swizzle
__device__ __forceinline__ uint32_t swzH(int row, int chunk) {
    return (uint32_t)((row << 6) + (((chunk ^ ((row >> 1) & 3)) & 3) << 4));
}

// ===================== preprocessing kernels =====================
// conv_w [oc][ic][tap] -> g_wh [oc][tap*256+ic]
__global__ __launch_bounds__(1024) void convW_kernel(const float* __restrict__ W) {
    int j = blockIdx.x * 1024 + threadIdx.x;
    if (j < 256 * 2304) {
        int oc = j / 2304, rem = j - oc * 2304;
        int tap = rem >> 8, ic = rem & 255;
        g_wh[j] = __float2half(W[oc * 2304 + ic * 9 + tap]);
    }
}

// head weights -> pre-swizzled tiles g_hb[ks][o][chunk swz]
__global__ __launch_bounds__(256) void convHW_kernel(
    const float* __restrict__ cls_w, const float* __restrict__ box_w) {
    for (int it = 0; it < 10; it++) {
        int q = it * 256 + threadIdx.x;           // chunk id, 2560 total
        int ks = q / 320, rem = q - ks * 320;
        int o = rem >> 2, ch = rem & 3;
        __half v[8];
        #pragma unroll
        for (int i = 0; i < 8; i++) {
            int k = ks * 32 + ch * 8 + i;
            float w = 0.f;
            if (o < 15)      w = cls_w[o * 256 + k];
            else if (o < 75) w = box_w[(o - 15) * 256 + k];
            v[i] = __float2half(w);
        }
        char* dst = (char*)g_hb + ks * 5120 + o * 64
                  + (((ch ^ ((o >> 1) & 3)) & 3) << 4);
        *(uint4*)dst = *(uint4*)v;
    }
}

// feats [b][c][g2] -> g_fh [b][px][c] half
__global__ __launch_bounds__(256) void convF_kernel(
    const float* __restrict__ f0, const float* __restrict__ f1,
    const float* __restrict__ f2, const float* __restrict__ f3,
    const float* __restrict__ f4)
{
    const int b = blockIdx.y;
    const int px = blockIdx.x * 256 + threadIdx.x;
    if (px >= P_TOT) return;
    int g2, lvl_off; const float* feat;
    if      (px < 16384) { g2 = 16384; lvl_off = 0;     feat = f0; }
    else if (px < 20480) { g2 = 4096;  lvl_off = 16384; feat = f1; }
    else if (px < 21504) { g2 = 1024;  lvl_off = 20480; feat = f2; }
    else if (px < 21760) { g2 = 256;   lvl_off = 21504; feat = f3; }
    else                 { g2 = 64;    lvl_off = 21760; feat = f4; }
    const int lp = px - lvl_off;
    const float* src = feat + (size_t)b * 256 * g2 + lp;
    __half* dst = g_th, *drow = g_fh + ((size_t)b * P_TOT + px) * 256;
    (void)dst;
    for (int c0 = 0; c0 < 256; c0 += 8) {
        __half v[8];
        #pragma unroll
        for (int i = 0; i < 8; i++)
            v[i] = __float2half(src[(size_t)(c0 + i) * g2]);
        *(uint4*)(drow + c0) = *(uint4*)v;
    }
}

// ===================== fp16 mma implicit-GEMM conv =====================
// D[128 px, 128 oc] += A[px,k'] * W[og*128+oc,k'], k' = tap*256 + ic
__global__ __launch_bounds__(256, 2) void conv_mma(const float* __restrict__ bias)
{
    extern __shared__ __align__(16) char smem[];
    const uint32_t smem_b = smem_u32(smem);
    const int t = threadIdx.x, lane = t & 31, warp = t >> 5;
    const int og = blockIdx.y;

    // ---- tile decode ----
    int tp = blockIdx.x;
    int b = 0;
    if (tp >= 171) { b = 1; tp -= 171; }
    int g, lg, gpix0, lvl_off, nvalid = 128;
    if      (tp < 128) { g = 128; lg = 7; lvl_off = 0;     gpix0 = tp * 128; }
    else if (tp < 160) { g = 64;  lg = 6; lvl_off = 16384; gpix0 = 16384 + (tp - 128) * 128; }
    else if (tp < 168) { g = 32;  lg = 5; lvl_off = 20480; gpix0 = 20480 + (tp - 160) * 128; }
    else if (tp < 170) { g = 16;  lg = 4; lvl_off = 21504; gpix0 = 21504 + (tp - 168) * 128; }
    else               { g = 8;   lg = 3; lvl_off = 21760; gpix0 = 21760; nvalid = 64; }

    // ---- per-thread A source: row grow, k-half kh ----
    const int grow = t >> 1, kh = t & 1;
    const bool vm = grow < nvalid;
    const int pl = gpix0 - lvl_off + grow;
    const int pi = pl >> lg, pj = pl & (g - 1);
    unsigned tmask = 0;
    #pragma unroll
    for (int dr = 0; dr < 3; dr++)
        #pragma unroll
        for (int dc = 0; dc < 3; dc++) {
            int ii = pi + dr - 1, jj = pj + dc - 1;
            if (vm && (unsigned)ii < (unsigned)g && (unsigned)jj < (unsigned)g)
                tmask |= 1u << (dr * 3 + dc);
        }
    const char* rowBase = (const char*)(g_fh
        + (((size_t)b * P_TOT + lvl_off) + (size_t)pi * g + pj) * 256) + kh * 32;
    const int gRow = g * 512;   // bytes per grid row in NHWC

    // ---- B source ----
    const int brow = t >> 1;
    const char* wsrc = (const char*)(g_wh + (size_t)(og * 128 + brow) * 2304)
                     + kh * 32;

    auto fill = [&](int s) {
        const int buf = s & 3;
        const int tap = s >> 3, ic0 = (s & 7) * 32;
        const int dr = (tap * 11) >> 5, dc = tap - dr * 3;
        uint32_t sz = ((tmask >> tap) & 1) ? 16u : 0u;
        const char* srcA = sz ? (rowBase + (dr - 1) * gRow + (dc - 1) * 512
                                 + ic0 * 2)
                              : (const char*)g_fh;
        uint32_t Ab = smem_b + buf * 16384;
        uint32_t Bb = Ab + 8192;
        const char* srcB = wsrc + s * 64;
        #pragma unroll
        for (int j = 0; j < 2; j++) {
            cp_async16z(Ab + swzH(grow, 2 * kh + j), srcA + j * 16, sz);
            cp_async16(Bb + swzH(brow, 2 * kh + j), srcB + j * 16);
        }
    };

    // ---- warp tiling: 4(M) x 2(N), warp tile 32x64 ----
    const int m0 = (warp & 3) * 32, n0 = (warp >> 2) * 64;
    float acc[2][8][4];
    #pragma unroll
    for (int i = 0; i < 2; i++)
        #pragma unroll
        for (int j = 0; j < 8; j++)
            #pragma unroll
            for (int q = 0; q < 4; q++) acc[i][j][q] = 0.f;

    // ---- prologue: 3 stages in flight ----
    fill(0); CP_COMMIT();
    fill(1); CP_COMMIT();
    fill(2); CP_COMMIT();

    // ---- mainloop ----
    for (int s = 0; s < NSTAGE; s++) {
        const int buf = s & 3;
        CP_WAIT(2);
        __syncthreads();
        if (s + 3 < NSTAGE) fill(s + 3);
        CP_COMMIT();

        const uint32_t As = smem_b + buf * 16384;
        const uint32_t Bs = As + 8192;
        #pragma unroll
        for (int k16 = 0; k16 < 2; k16++) {
            uint32_t a[2][4];
            #pragma unroll
            for (int mt = 0; mt < 2; mt++)
                ldm4(a[mt], As + swzH(m0 + mt * 16 + (lane & 15),
                                      k16 * 2 + (lane >> 4)));
            #pragma unroll
            for (int np = 0; np < 4; np++) {
                uint32_t bb[4];
                ldm4(bb, Bs + swzH(n0 + np * 16 + ((lane >> 4) & 1) * 8 + (lane & 7),
                                   k16 * 2 + ((lane >> 3) & 1)));
                mma_f16(acc[0][2 * np],     a[0], bb[0], bb[1]);
                mma_f16(acc[1][2 * np],     a[1], bb[0], bb[1]);
                mma_f16(acc[0][2 * np + 1], a[0], bb[2], bb[3]);
                mma_f16(acc[1][2 * np + 1], a[1], bb[2], bb[3]);
            }
        }
        __syncthreads();
    }

    // ---- epilogue: bias + ReLU -> g_th [b][px][oc] half2 ----
    #pragma unroll
    for (int mt = 0; mt < 2; mt++) {
        int r0 = m0 + mt * 16 + (lane >> 2);
        #pragma unroll
        for (int half = 0; half < 2; half++) {
            int r = r0 + half * 8;
            if (r < nvalid) {
                __half* drow = g_th + ((size_t)b * P_TOT + gpix0 + r) * 256;
                #pragma unroll
                for (int nt = 0; nt < 8; nt++) {
                    int c = n0 + nt * 8 + 2 * (lane & 3);
                    int oc = og * 128 + c;
                    float v0 = fmaxf(acc[mt][nt][half * 2 + 0] + __ldg(&bias[oc]), 0.f);
                    float v1 = fmaxf(acc[mt][nt][half * 2 + 1] + __ldg(&bias[oc + 1]), 0.f);
                    *(__half2*)(drow + oc) = __floats2half2_rn(v0, v1);
                }
            }
        }
    }
}

// ---------------------------------------------------------------------------
// Head via fp16 mma: per block 128 px x 80 outs, K=256 (8 stages of 32).
// 4 warps: warp covers rows m0..m0+31, all 80 cols.
// ---------------------------------------------------------------------------
__global__ __launch_bounds__(128) void head_mma(
    const float* __restrict__ cls_b, const float* __restrict__ box_b,
    float* __restrict__ preds)
{
    extern __shared__ __align__(16) char smem[];
    const uint32_t smem_b = smem_u32(smem);       // B tiles 40960B, then A 2x8192
    const uint32_t Bbase = smem_b;
    const uint32_t Abase = smem_b + 40960;
    const int t = threadIdx.x, lane = t & 31, warp = t >> 5;
    const int b = blockIdx.y;
    const int gpx0 = blockIdx.x * 128;

    int g2, lvl_off, nvalid = 128;
    if      (gpx0 < 16384) { g2 = 16384; lvl_off = 0; }
    else if (gpx0 < 20480) { g2 = 4096;  lvl_off = 16384; }
    else if (gpx0 < 21504) { g2 = 1024;  lvl_off = 20480; }
    else if (gpx0 < 21760) { g2 = 256;   lvl_off = 21504; }
    else                   { g2 = 64;    lvl_off = 21760; nvalid = 64; }

    // B: whole 40KB via cp.async (128 thr x 20 chunks)
    {
        const char* src = (const char*)g_hb;
        #pragma unroll
        for (int i = 0; i < 20; i++) {
            int q = i * 128 + t;
            cp_async16(Bbase + q * 16, src + q * 16);
        }
    }
    // A fill: thread owns px row t; 4 chunks per stage
    const char* arow = (const char*)(g_th + ((size_t)b * P_TOT + gpx0 + t) * 256);
    const uint32_t asz = (t < nvalid) ? 16u : 0u;
    auto fillA = [&](int ks) {
        uint32_t Ab = Abase + (ks & 1) * 8192;
        const char* src = asz ? (arow + ks * 64) : (const char*)g_th;
        #pragma unroll
        for (int j = 0; j < 4; j++)
            cp_async16z(Ab + swzH(t, j), src + j * 16, asz);
    };
    fillA(0);
    CP_COMMIT();                                   // G0 = B + A0

    const int m0 = warp * 32;
    float acc[2][10][4];
    #pragma unroll
    for (int i = 0; i < 2; i++)
        #pragma unroll
        for (int j = 0; j < 10; j++)
            #pragma unroll
            for (int q = 0; q < 4; q++) acc[i][j][q] = 0.f;

    for (int ks = 0; ks < 8; ks++) {
        if (ks + 1 < 8) { fillA(ks + 1); CP_COMMIT(); }
        if (ks + 1 < 8) CP_WAIT(1); else CP_WAIT(0);
        __syncthreads();

        const uint32_t As = Abase + (ks & 1) * 8192;
        const uint32_t Bs = Bbase + ks * 5120;
        #pragma unroll
        for (int k16 = 0; k16 < 2; k16++) {
            uint32_t a[2][4];
            #pragma unroll
            for (int mt = 0; mt < 2; mt++)
                ldm4(a[mt], As + swzH(m0 + mt * 16 + (lane & 15),
                                      k16 * 2 + (lane >> 4)));
            #pragma unroll
            for (int np = 0; np < 5; np++) {
                uint32_t bb[4];
                ldm4(bb, Bs + swzH(np * 16 + ((lane >> 4) & 1) * 8 + (lane & 7),
                                   k16 * 2 + ((lane >> 3) & 1)));
                mma_f16(acc[0][2 * np],     a[0], bb[0], bb[1]);
                mma_f16(acc[1][2 * np],     a[1], bb[0], bb[1]);
                mma_f16(acc[0][2 * np + 1], a[0], bb[2], bb[3]);
                mma_f16(acc[1][2 * np + 1], a[1], bb[2], bb[3]);
            }
        }
        __syncthreads();
    }

    // epilogue -> preds
    const long base_r = 15L * lvl_off;
    #pragma unroll
    for (int mt = 0; mt < 2; mt++) {
        int r0 = m0 + mt * 16 + (lane >> 2);
        #pragma unroll
        for (int half = 0; half < 2; half++) {
            int r = r0 + half * 8;
            if (r < nvalid) {
                int lp = gpx0 + r - lvl_off;
                #pragma unroll
                for (int nt = 0; nt < 10; nt++) {
                    #pragma unroll
                    for (int e = 0; e < 2; e++) {
                        int o = nt * 8 + 2 * (lane & 3) + e;
                        if (o < 75) {
                            int a, slot; float bv;
                            if (o < 15) { a = o; slot = 0; bv = __ldg(&cls_b[o]); }
                            else { int cc = o - 15; a = cc >> 2; slot = 1 + (cc & 3);
                                   bv = __ldg(&box_b[cc]); }
                            size_t rr = (size_t)base_r + (size_t)a * g2 + lp;
                            preds[((size_t)b * R_TOT + rr) * 5 + slot] =
                                acc[mt][nt][half * 2 + e] + bv;
                        }
                    }
                }
            }
        }
    }
}

// ---------------------------------------------------------------------------
// Anchor labeling (unchanged, verified)
// ---------------------------------------------------------------------------
__global__ __launch_bounds__(256) void label_kernel(
    const float* __restrict__ gt, float* __restrict__ labels,
    float* __restrict__ matched)
{
    __shared__ float4 gq[32];
    __shared__ float  ga[32];
    __shared__ unsigned long long skey[32];
    const int t = threadIdx.x;
    const int b = blockIdx.y;
    if (t < 32) {
        const float* p = gt + ((size_t)b * 32 + t) * 4;
        float x = p[0], y = p[1], w = p[2], h = p[3];
        float4 q = make_float4(x, y, x + w, y + h);
        gq[t] = q;
        ga[t] = (q.z - q.x) * (q.w - q.y);
        skey[t] = 0ull;
    }
    __syncthreads();

    const int r = blockIdx.x * 256 + t;
    const bool active = r < R_TOT;

    float ax1 = 0.f, ay1 = 0.f, ax2 = 1.f, ay2 = 1.f;
    if (active) {
        int base, g, shift; float stride;
        if      (r < 245760) { base = 0;      g = 128; shift = 14; stride = 4.f;  }
        else if (r < 307200) { base = 245760; g = 64;  shift = 12; stride = 8.f;  }
        else if (r < 322560) { base = 307200; g = 32;  shift = 10; stride = 16.f; }
        else if (r < 326400) { base = 322560; g = 16;  shift = 8;  stride = 32.f; }
        else                 { base = 326400; g = 8;   shift = 6;  stride = 64.f; }
        int rl = r - base;
        int a   = rl >> shift;
        int pix = rl & ((1 << shift) - 1);
        int i = pix >> (shift >> 1);
        int j = pix & (g - 1);
        int rm = a % 3;
        double rs = (rm == 0) ? 0.7071067811865476
                  : (rm == 1) ? 1.0 : 1.4142135623730951;
        float sz = (float)(32 << (a / 3));
        float aw = (float)((double)sz * rs);
        float ah = (float)((double)sz / rs);
        float cx = i * stride, cy = j * stride;
        float hw = aw * 0.5f, hh = ah * 0.5f;
        ax1 = cx - hw; ay1 = cy - hh; ax2 = cx + hw; ay2 = cy + hh;
    }
    float areaA = (ax2 - ax1) * (ay2 - ay1);
    float best = -1.f; int barg = 0;
    const unsigned rkey = active ? (unsigned)(~(unsigned)r) : 0u;

    #pragma unroll 4
    for (int n = 0; n < 32; n++) {
        float4 q = gq[n];
        float lx = fmaxf(ax1, q.x), ly = fmaxf(ay1, q.y);
        float rx = fminf(ax2, q.z), ry = fminf(ay2, q.w);
        float w  = fmaxf(rx - lx, 0.f), h = fmaxf(ry - ly, 0.f);
        float inter = w * h;
        float iou = inter / (areaA + ga[n] - inter);
        if (iou > best) { best = iou; barg = n; }
        unsigned long long key = active
            ? ((((unsigned long long)__float_as_uint(iou)) << 32) | rkey)
            : 0ull;
        #pragma unroll
        for (int off = 16; off; off >>= 1) {
            unsigned long long o = __shfl_down_sync(0xffffffffu, key, off);
            if (o > key) key = o;
        }
        if ((t & 31) == 0) atomicMax(&skey[n], key);
    }

    if (active) {
        float lab = (best < 0.3f) ? 0.f : ((best > 0.7f) ? 1.f : -1.f);
        labels[(size_t)b * R_TOT + r] = lab;
        float4 mm = gq[barg];
        float* mp = matched + ((size_t)b * R_TOT + r) * 4;
        mp[0] = mm.x; mp[1] = mm.y; mp[2] = mm.z; mp[3] = mm.w;
    }
    __syncthreads();
    if (t < 32)
        g_part[((size_t)b * NB_LBL + blockIdx.x) * 32 + t] = skey[t];
}

__global__ __launch_bounds__(256) void fixup_kernel(float* __restrict__ labels)
{
    const int b = blockIdx.x >> 5;
    const int n = blockIdx.x & 31;
    unsigned long long best = 0ull;
    for (int i = threadIdx.x; i < NB_LBL; i += 256) {
        unsigned long long v = g_part[((size_t)b * NB_LBL + i) * 32 + n];
        if (v > best) best = v;
    }
    __shared__ unsigned long long sred[256];
    sred[threadIdx.x] = best;
    __syncthreads();
    for (int s = 128; s; s >>= 1) {
        if (threadIdx.x < s) {
            if (sred[threadIdx.x + s] > sred[threadIdx.x])
                sred[threadIdx.x] = sred[threadIdx.x + s];
        }
        __syncthreads();
    }
    if (threadIdx.x == 0) {
        unsigned rr = ~((unsigned)(sred[0] & 0xffffffffull));
        float* L = labels + (size_t)b * R_TOT + rr;
        if (*L != 0.f) *L = 1.f;
    }
}

// ---------------------------------------------------------------------------
extern "C" void kernel_launch(void* const* d_in, const int* in_sizes, int n_in,
                              void* d_out, int out_size)
{
    (void)in_sizes; (void)n_in; (void)out_size;
    const float* f0     = (const float*)d_in[1];
    const float* f1     = (const float*)d_in[2];
    const float* f2     = (const float*)d_in[3];
    const float* f3     = (const float*)d_in[4];
    const float* f4     = (const float*)d_in[5];
    const float* gt     = (const float*)d_in[6];
    const float* conv_w = (const float*)d_in[7];
    const float* conv_b = (const float*)d_in[8];
    const float* cls_w  = (const float*)d_in[9];
    const float* cls_b  = (const float*)d_in[10];
    const float* box_w  = (const float*)d_in[11];
    const float* box_b  = (const float*)d_in[12];

    float* preds   = (float*)d_out;                       // [2,R,5]
    float* labels  = preds + (size_t)2 * R_TOT * 5;       // [2,R]
    float* matched = labels + (size_t)2 * R_TOT;          // [2,R,4]

    convW_kernel<<<576, 1024>>>(conv_w);
    convHW_kernel<<<1, 256>>>(cls_w, box_w);
    convF_kernel<<<dim3(86, 2), 256>>>(f0, f1, f2, f3, f4);

    cudaFuncSetAttribute(conv_mma, cudaFuncAttributeMaxDynamicSharedMemorySize,
                         65536);
    conv_mma<<<dim3(342, 2), 256, 65536>>>(conv_b);

    cudaFuncSetAttribute(head_mma, cudaFuncAttributeMaxDynamicSharedMemorySize,
                         57344);
    head_mma<<<dim3(171, 2), 128, 57344>>>(cls_b, box_b, preds);

    label_kernel<<<dim3(NB_LBL, 2), 256>>>(gt, labels, matched);
    fixup_kernel<<<64, 256>>>(labels);
}